// round 1
// baseline (speedup 1.0000x reference)
#include <cuda_runtime.h>
#include <math.h>

#define SQRT2F 1.41421356237309515f
#define INV_SQRT2F 0.70710678118654752f

// ---------------- scratch (static device globals; no allocation) ----------------
__device__ float g_y  [8u*256u*64u*64u];     // conv1 output (lrelu'd)          33.5 MB
__device__ float g_up [8u*256u*128u*128u];   // upsampled conv1 output          134 MB
__device__ float g_upx[8u*256u*128u*128u];   // upsampled x (skip path)         134 MB
__device__ float g_wT1[256*9*256];           // w1 transposed [ci][tap][co] * scale
__device__ float g_wT2[256*9*128];           // w2 transposed [ci][tap][co] * scale
__device__ float g_wskT[256*128];            // w_skip transposed [ci][co] * scale

// ---------------- weight prep: transpose + fold equalized-lr scale ----------------
__global__ void prep_weights(const float* __restrict__ w1,
                             const float* __restrict__ w2,
                             const float* __restrict__ wsk) {
    int i = blockIdx.x * 256 + threadIdx.x;
    const float s3 = 1.0f / 48.0f;   // 1/sqrt(256*9)
    const float s1 = 0.0625f;        // 1/sqrt(256)
    if (i < 256 * 256 * 9) {
        int co  = i / (256 * 9);
        int rem = i % (256 * 9);
        int ci  = rem / 9;
        int tap = rem % 9;
        g_wT1[(ci * 9 + tap) * 256 + co] = w1[i] * s3;
    }
    if (i < 128 * 256 * 9) {
        int co  = i / (256 * 9);
        int rem = i % (256 * 9);
        int ci  = rem / 9;
        int tap = rem % 9;
        g_wT2[(ci * 9 + tap) * 128 + co] = w2[i] * s3;
    }
    if (i < 128 * 256) {
        int co = i / 256;
        int ci = i % 256;
        g_wskT[ci * 128 + co] = wsk[i] * s1;
    }
}

// ---------------- conv3x3 pad=1 + bias + FusedLeakyReLU ----------------
// Block tile: 64 output channels x (8 rows x 16 cols) spatial.
// Thread tile: 8 co x 4 cols (256 threads: co_t=tid&7, sp_t=tid>>3; row=sp_t>>2, cg=sp_t&3)
template<int CIN, int COUT, int H, int W>
__global__ __launch_bounds__(256)
void conv3x3_lrelu(const float* __restrict__ in, const float* __restrict__ wT,
                   const float* __restrict__ bias, float* __restrict__ out) {
    constexpr int TW = 16, TH = 8, CB = 8, BCO = 64;
    __shared__ float s_in[CB][TH + 2][TW + 2];   // 8*10*18 = 1440 fl
    __shared__ float s_w[CB][9][BCO];            // 8*9*64  = 4608 fl

    const int tid  = threadIdx.x;
    const int co_t = tid & 7;
    const int sp_t = tid >> 3;
    const int row  = sp_t >> 2;   // 0..7
    const int cg   = sp_t & 3;    // 0..3 (col group of 4)

    const int tiles_w = W / TW;
    const int n   = blockIdx.z;
    const int co0 = blockIdx.y * BCO;
    const int h0  = (blockIdx.x / tiles_w) * TH;
    const int w0  = (blockIdx.x % tiles_w) * TW;

    float acc[8][4];
    #pragma unroll
    for (int o = 0; o < 8; o++)
        #pragma unroll
        for (int s = 0; s < 4; s++) acc[o][s] = 0.0f;

    const float* in_n = in + (size_t)n * CIN * H * W;

    for (int c0 = 0; c0 < CIN; c0 += CB) {
        // stage input tile (with halo + zero pad)
        for (int i = tid; i < CB * (TH + 2) * (TW + 2); i += 256) {
            int ci  = i / ((TH + 2) * (TW + 2));
            int rem = i % ((TH + 2) * (TW + 2));
            int r = rem / (TW + 2);
            int c = rem % (TW + 2);
            int h = h0 + r - 1, w = w0 + c - 1;
            float v = 0.0f;
            if (h >= 0 && h < H && w >= 0 && w < W)
                v = in_n[((size_t)(c0 + ci) * H + h) * W + w];
            s_in[ci][r][c] = v;
        }
        // stage weights (coalesced: inner index is co)
        for (int i = tid; i < CB * 9 * BCO; i += 256) {
            int ci  = i / (9 * BCO);
            int rem = i % (9 * BCO);
            ((float*)s_w)[i] =
                wT[(size_t)(c0 + ci) * 9 * COUT + (rem / BCO) * COUT + co0 + (rem % BCO)];
        }
        __syncthreads();

        #pragma unroll
        for (int ci = 0; ci < CB; ci++) {
            float iv[3][6];
            #pragma unroll
            for (int ky = 0; ky < 3; ky++)
                #pragma unroll
                for (int c = 0; c < 6; c++)
                    iv[ky][c] = s_in[ci][row + ky][cg * 4 + c];

            #pragma unroll
            for (int ky = 0; ky < 3; ky++)
                #pragma unroll
                for (int kx = 0; kx < 3; kx++) {
                    float wv[8];
                    #pragma unroll
                    for (int o = 0; o < 8; o++) wv[o] = s_w[ci][ky * 3 + kx][o * 8 + co_t];
                    #pragma unroll
                    for (int o = 0; o < 8; o++)
                        #pragma unroll
                        for (int s = 0; s < 4; s++)
                            acc[o][s] = fmaf(wv[o], iv[ky][kx + s], acc[o][s]);
                }
        }
        __syncthreads();
    }

    // epilogue: bias + leaky relu * sqrt(2), vectorized store
    #pragma unroll
    for (int o = 0; o < 8; o++) {
        int co = co0 + o * 8 + co_t;
        float b = bias[co];
        float4 v;
        float* vp = (float*)&v;
        #pragma unroll
        for (int s = 0; s < 4; s++) {
            float y = acc[o][s] + b;
            y = (y >= 0.0f ? y : 0.2f * y) * SQRT2F;
            vp[s] = y;
        }
        *(float4*)&out[(((size_t)n * COUT + co) * H + (h0 + row)) * W + w0 + cg * 4] = v;
    }
}

// ---------------- bilinear 2x upsample (half-pixel, edge-clamped) ----------------
// matches jax.image.resize(..., 'bilinear') / torch align_corners=False for scale 2:
//   out[2m]   = 0.25*y[m-1] + 0.75*y[m]   (m-1 clamped)
//   out[2m+1] = 0.75*y[m]   + 0.25*y[m+1] (m+1 clamped)
template<int HI>
__global__ __launch_bounds__(256)
void upsample2x(const float* __restrict__ in, float* __restrict__ out) {
    constexpr int HO = 2 * HI;
    size_t idx = (size_t)blockIdx.x * 256 + threadIdx.x;
    int ow = (int)(idx & (HO - 1));
    int oh = (int)((idx >> 7) & (HO - 1));     // HO = 128 -> shift 7
    size_t nc = idx >> 14;                     // / (128*128)

    int mh = oh >> 1;
    int h0, h1; float fh0, fh1;
    if (oh & 1) { h0 = mh; h1 = (mh + 1 < HI) ? mh + 1 : HI - 1; fh0 = 0.75f; fh1 = 0.25f; }
    else        { h0 = (mh > 0) ? mh - 1 : 0; h1 = mh;           fh0 = 0.25f; fh1 = 0.75f; }

    int mw = ow >> 1;
    int w0, w1; float fw0, fw1;
    if (ow & 1) { w0 = mw; w1 = (mw + 1 < HI) ? mw + 1 : HI - 1; fw0 = 0.75f; fw1 = 0.25f; }
    else        { w0 = (mw > 0) ? mw - 1 : 0; w1 = mw;           fw0 = 0.25f; fw1 = 0.75f; }

    const float* p = in + nc * HI * HI;
    float v = fh0 * (fw0 * p[h0 * HI + w0] + fw1 * p[h0 * HI + w1])
            + fh1 * (fw0 * p[h1 * HI + w0] + fw1 * p[h1 * HI + w1]);
    out[idx] = v;
}

// ---------------- skip 1x1 conv + final combine: out = (out + skip)/sqrt(2) ----------------
// Block: 128 co (all) x 64 spatial; thread: 8 co x 4 sp (co_t=tid&15, sp_t=tid>>4)
__global__ __launch_bounds__(256)
void skip_combine(const float* __restrict__ upx, const float* __restrict__ wT,
                  float* __restrict__ out) {
    constexpr int CB = 8, HW = 128 * 128, CIN = 256, COUT = 128, SP = 64;
    __shared__ float s_x[CB][SP];
    __shared__ float s_w[CB][COUT];

    const int tid  = threadIdx.x;
    const int co_t = tid & 15;
    const int sp_t = tid >> 4;
    const int n    = blockIdx.z;
    const int p0   = blockIdx.x * SP;

    float acc[8][4];
    #pragma unroll
    for (int o = 0; o < 8; o++)
        #pragma unroll
        for (int s = 0; s < 4; s++) acc[o][s] = 0.0f;

    const float* xn = upx + (size_t)n * CIN * HW;

    for (int c0 = 0; c0 < CIN; c0 += CB) {
        for (int i = tid; i < CB * SP; i += 256) {
            int ci = i / SP, p = i % SP;
            s_x[ci][p] = xn[(size_t)(c0 + ci) * HW + p0 + p];
        }
        for (int i = tid; i < CB * COUT; i += 256) {
            int ci = i / COUT, co = i % COUT;
            s_w[ci][co] = wT[(c0 + ci) * COUT + co];
        }
        __syncthreads();
        #pragma unroll
        for (int ci = 0; ci < CB; ci++) {
            float xv[4];
            #pragma unroll
            for (int s = 0; s < 4; s++) xv[s] = s_x[ci][sp_t * 4 + s];
            #pragma unroll
            for (int o = 0; o < 8; o++) {
                float wv = s_w[ci][o * 16 + co_t];
                #pragma unroll
                for (int s = 0; s < 4; s++) acc[o][s] = fmaf(wv, xv[s], acc[o][s]);
            }
        }
        __syncthreads();
    }

    #pragma unroll
    for (int o = 0; o < 8; o++) {
        int co = o * 16 + co_t;
        size_t base = ((size_t)n * COUT + co) * HW + p0 + sp_t * 4;
        float4 prev = *(const float4*)&out[base];
        float4 v;
        v.x = (prev.x + acc[o][0]) * INV_SQRT2F;
        v.y = (prev.y + acc[o][1]) * INV_SQRT2F;
        v.z = (prev.z + acc[o][2]) * INV_SQRT2F;
        v.w = (prev.w + acc[o][3]) * INV_SQRT2F;
        *(float4*)&out[base] = v;
    }
}

// ---------------- launch ----------------
extern "C" void kernel_launch(void* const* d_in, const int* in_sizes, int n_in,
                              void* d_out, int out_size) {
    const float* x   = (const float*)d_in[0];
    const float* w1  = (const float*)d_in[1];
    const float* b1  = (const float*)d_in[2];
    const float* w2  = (const float*)d_in[3];
    const float* b2  = (const float*)d_in[4];
    const float* wsk = (const float*)d_in[5];
    float* out = (float*)d_out;

    float *p_y, *p_up, *p_upx, *p_wT1, *p_wT2, *p_wskT;
    cudaGetSymbolAddress((void**)&p_y,    g_y);
    cudaGetSymbolAddress((void**)&p_up,   g_up);
    cudaGetSymbolAddress((void**)&p_upx,  g_upx);
    cudaGetSymbolAddress((void**)&p_wT1,  g_wT1);
    cudaGetSymbolAddress((void**)&p_wT2,  g_wT2);
    cudaGetSymbolAddress((void**)&p_wskT, g_wskT);

    // 0) weight transpose + scale fold
    prep_weights<<<(256 * 256 * 9 + 255) / 256, 256>>>(w1, w2, wsk);

    // 1) conv1 (256->256, 64x64) + lrelu -> g_y
    conv3x3_lrelu<256, 256, 64, 64><<<dim3(32, 4, 8), 256>>>(x, p_wT1, b1, p_y);

    // 2) bilinear up x2 of conv1 output -> g_up  (8*256*128*128 elements)
    upsample2x<64><<<(8u * 256u * 128u * 128u) / 256u, 256>>>(p_y, p_up);

    // 3) conv2 (256->128, 128x128) + lrelu -> d_out
    conv3x3_lrelu<256, 128, 128, 128><<<dim3(128, 2, 8), 256>>>(p_up, p_wT2, b2, out);

    // 4) bilinear up x2 of x -> g_upx
    upsample2x<64><<<(8u * 256u * 128u * 128u) / 256u, 256>>>(x, p_upx);

    // 5) skip 1x1 conv + combine into d_out
    skip_combine<<<dim3(16384 / 64, 1, 8), 256>>>(p_upx, p_wskT, out);
}